// round 1
// baseline (speedup 1.0000x reference)
#include <cuda_runtime.h>
#include <math.h>

#define Bsz 4
#define Nn 2048
#define Cc 64
#define Pp 48
#define Ee 128
#define Kk 3072            // C*P
#define Mm 16384           // 2*B*N rows (sig half then mem half)
#define HALF_WIN 15

// ---------------- scratch ----------------
__device__ float g_embed[Mm * Ee];           // 8 MB, pre-BN then normalized in-place
__device__ float g_psum[2 * 64 * Ee];        // BN partial sums
__device__ float g_psumsq[2 * 64 * Ee];
__device__ float g_scale[2 * Ee];
__device__ float g_shift[2 * Ee];
__device__ float g_attn_band[Bsz * Nn * 32]; // band attn, stride 32

// ---------------- K1: embed GEMM  y[m,e] = sum_k X[m,k] w[e,k] + b[e] ----------------
// BM=64, BN=128(=E), BK=16, 256 threads, thread tile 4x8
__global__ void k_gemm(const float* __restrict__ sig, const float* __restrict__ mem,
                       const float* __restrict__ w, const float* __restrict__ bias) {
    __shared__ float As[16][64];
    __shared__ float Bs[16][128];
    int bm = blockIdx.x * 64;
    const float* X = (bm < 8192) ? sig : mem;
    int rb = (bm < 8192) ? bm : bm - 8192;
    int tid = threadIdx.x;
    int tx = tid & 15;      // N dim: 8 cols each
    int ty = tid >> 4;      // M dim: 4 rows each
    float acc[4][8];
#pragma unroll
    for (int i = 0; i < 4; i++)
#pragma unroll
        for (int j = 0; j < 8; j++) acc[i][j] = 0.f;

    for (int k0 = 0; k0 < Kk; k0 += 16) {
        // load A tile: 64 rows x 16 k = 256 float4
        {
            int m = tid >> 2;
            int k4 = (tid & 3) * 4;
            float4 v = *(const float4*)&X[(size_t)(rb + m) * Kk + k0 + k4];
            As[k4 + 0][m] = v.x; As[k4 + 1][m] = v.y; As[k4 + 2][m] = v.z; As[k4 + 3][m] = v.w;
        }
        // load W tile: 128 rows x 16 k = 512 float4, 2 per thread
#pragma unroll
        for (int i = 0; i < 2; i++) {
            int p = tid + i * 256;
            int e = p >> 2;
            int k4 = (p & 3) * 4;
            float4 v = *(const float4*)&w[(size_t)e * Kk + k0 + k4];
            Bs[k4 + 0][e] = v.x; Bs[k4 + 1][e] = v.y; Bs[k4 + 2][e] = v.z; Bs[k4 + 3][e] = v.w;
        }
        __syncthreads();
#pragma unroll
        for (int kk = 0; kk < 16; kk++) {
            float4 a4 = *(float4*)&As[kk][ty * 4];
            float4 b0 = *(float4*)&Bs[kk][tx * 8];
            float4 b1 = *(float4*)&Bs[kk][tx * 8 + 4];
            float a[4] = {a4.x, a4.y, a4.z, a4.w};
            float bb[8] = {b0.x, b0.y, b0.z, b0.w, b1.x, b1.y, b1.z, b1.w};
#pragma unroll
            for (int i = 0; i < 4; i++)
#pragma unroll
                for (int j = 0; j < 8; j++) acc[i][j] += a[i] * bb[j];
        }
        __syncthreads();
    }
#pragma unroll
    for (int i = 0; i < 4; i++) {
        int m = bm + ty * 4 + i;
#pragma unroll
        for (int j = 0; j < 8; j++) {
            int e = tx * 8 + j;
            g_embed[m * Ee + e] = acc[i][j] + bias[e];
        }
    }
}

// ---------------- K2: BN partial sums (deterministic) ----------------
// grid (64, 2), 128 threads; each block sums 128 rows of its half
__global__ void k_bn_stats() {
    int e = threadIdx.x;
    int chunk = blockIdx.x;
    int half = blockIdx.y;
    int row0 = half * 8192 + chunk * 128;
    float s = 0.f, sq = 0.f;
#pragma unroll 4
    for (int r = 0; r < 128; r++) {
        float v = g_embed[(row0 + r) * Ee + e];
        s += v;
        sq += v * v;
    }
    g_psum[(half * 64 + chunk) * Ee + e] = s;
    g_psumsq[(half * 64 + chunk) * Ee + e] = sq;
}

// ---------------- K3: finalize BN scale/shift ----------------
__global__ void k_bn_final(const float* __restrict__ gamma, const float* __restrict__ beta) {
    int t = threadIdx.x; // 0..255
    int half = t >> 7;
    int e = t & 127;
    float s = 0.f, sq = 0.f;
    for (int c = 0; c < 64; c++) {
        s += g_psum[(half * 64 + c) * Ee + e];
        sq += g_psumsq[(half * 64 + c) * Ee + e];
    }
    float mean = s / 8192.f;
    float var = sq / 8192.f - mean * mean;
    float rstd = rsqrtf(var + 1e-5f);
    float sc = rstd * gamma[e];
    g_scale[t] = sc;
    g_shift[t] = beta[e] - mean * sc;
}

// ---------------- K4: apply BN + LeakyReLU in place ----------------
__global__ void k_bn_apply() {
    int idx = blockIdx.x * blockDim.x + threadIdx.x; // 2M threads
    if (idx >= Mm * Ee) return;
    int m = idx >> 7;
    int e = idx & 127;
    int half = m >> 13;
    float v = g_embed[idx] * g_scale[half * Ee + e] + g_shift[half * Ee + e];
    g_embed[idx] = (v >= 0.f) ? v : 0.1f * v;
}

// ---------------- K5: zero attn output ----------------
__global__ void k_zero(float* __restrict__ p, int n4) {
    int i = blockIdx.x * blockDim.x + threadIdx.x;
    float4 z = make_float4(0.f, 0.f, 0.f, 0.f);
    for (; i < n4; i += gridDim.x * blockDim.x) ((float4*)p)[i] = z;
}

// ---------------- K6: banded sim + softmax ----------------
// grid (N/8, B), 256 threads; warp per row
__global__ void k_attn(float* __restrict__ out_attn) {
    __shared__ float s_et[38 * 129];
    __shared__ float s_ex[8 * 128];
    int i0 = blockIdx.x * 8;
    int b = blockIdx.y;
    int jmin = max(0, i0 - HALF_WIN);
    int jmax = min(Nn - 1, i0 + 7 + HALF_WIN);
    int nj = jmax - jmin + 1;
    int tid = threadIdx.x;

    for (int p = tid; p < nj * 128; p += 256) {
        int jr = p >> 7, k = p & 127;
        s_et[jr * 129 + k] = g_embed[(8192 + b * Nn + jmin + jr) * Ee + k];
    }
    for (int p = tid; p < 8 * 128; p += 256) {
        int r = p >> 7, k = p & 127;
        s_ex[r * 128 + k] = g_embed[(b * Nn + i0 + r) * Ee + k];
    }
    __syncthreads();

    int w = tid >> 5, lane = tid & 31;
    int i = i0 + w;
    int j0 = max(0, i - HALF_WIN);
    int j1 = min(Nn - 1, i + HALF_WIN);
    int width = j1 - j0 + 1;

    float sim = -1e30f;
    if (lane < width) {
        int jr = j0 + lane - jmin;
        float acc = 0.f;
        const float* ex = &s_ex[w * 128];
        const float* et = &s_et[jr * 129];
#pragma unroll 8
        for (int k = 0; k < 128; k++) acc += ex[k] * et[k];
        sim = acc;
    }
    float mx = sim;
#pragma unroll
    for (int o = 16; o; o >>= 1) mx = fmaxf(mx, __shfl_xor_sync(0xffffffffu, mx, o));
    float ev = (lane < width) ? expf(sim - mx) : 0.f;
    float sum = ev;
#pragma unroll
    for (int o = 16; o; o >>= 1) sum += __shfl_xor_sync(0xffffffffu, sum, o);
    float a = ev / sum;
    if (lane < width) {
        out_attn[((size_t)(b * Nn + i)) * Nn + j0 + lane] = a;
        g_attn_band[(b * Nn + i) * 32 + lane] = a;
    }
}

// ---------------- K7: banded attn @ mem + blend ----------------
// grid (N/16, 12, B), 256 threads; block = 16 rows x 256 f; thread tile 4x4
__global__ void k_memw(const float* __restrict__ sig, const float* __restrict__ mem,
                       float* __restrict__ out_mem) {
    __shared__ float s_attn[16 * 48];
    __shared__ float s_val[23][256];
    int i0 = blockIdx.x * 16;
    int fc = blockIdx.y * 256;
    int b = blockIdx.z;
    int tid = threadIdx.x;
    int jmin = max(0, i0 - HALF_WIN);
    int jmax = min(Nn - 1, i0 + 15 + HALF_WIN);
    int nj = jmax - jmin + 1; // <= 46

    for (int q = tid; q < 16 * 48; q += 256) s_attn[q] = 0.f;
    __syncthreads();
    for (int q = tid; q < 16 * 32; q += 256) {
        int r = q >> 5, l = q & 31;
        int i = i0 + r;
        int j0 = max(0, i - HALF_WIN);
        int j1 = min(Nn - 1, i + HALF_WIN);
        if (l <= j1 - j0)
            s_attn[r * 48 + (j0 + l - jmin)] = g_attn_band[(b * Nn + i) * 32 + l];
    }
    __syncthreads();

    int tf = tid & 63;   // f group, 4 floats each
    int ti = tid >> 6;   // i group, 4 rows each
    float acc[4][4];
#pragma unroll
    for (int r = 0; r < 4; r++)
#pragma unroll
        for (int c = 0; c < 4; c++) acc[r][c] = 0.f;

    for (int s = 0; s * 23 < nj; s++) {
        int cnt = min(23, nj - s * 23);
        // stage cnt rows x 256 floats
        for (int p = tid; p < cnt * 64; p += 256) {
            int row = p >> 6, c4 = (p & 63) * 4;
            *(float4*)&s_val[row][c4] =
                *(const float4*)&mem[(size_t)(b * Nn + jmin + s * 23 + row) * Kk + fc + c4];
        }
        __syncthreads();
        for (int jl = 0; jl < cnt; jl++) {
            int jg = s * 23 + jl;
            float4 v = *(float4*)&s_val[jl][tf * 4];
#pragma unroll
            for (int r = 0; r < 4; r++) {
                float a = s_attn[(ti * 4 + r) * 48 + jg];
                acc[r][0] += a * v.x;
                acc[r][1] += a * v.y;
                acc[r][2] += a * v.z;
                acc[r][3] += a * v.w;
            }
        }
        __syncthreads();
    }

#pragma unroll
    for (int r = 0; r < 4; r++) {
        int i = i0 + ti * 4 + r;
        size_t base = (size_t)(b * Nn + i) * Kk + fc + tf * 4;
        float4 sg = *(const float4*)&sig[base];
        float4 o;
        o.x = 0.5f * sg.x + 0.5f * acc[r][0];
        o.y = 0.5f * sg.y + 0.5f * acc[r][1];
        o.z = 0.5f * sg.z + 0.5f * acc[r][2];
        o.w = 0.5f * sg.w + 0.5f * acc[r][3];
        *(float4*)&out_mem[base] = o;
    }
}

// ---------------- launch ----------------
extern "C" void kernel_launch(void* const* d_in, const int* in_sizes, int n_in,
                              void* d_out, int out_size) {
    const float* sig   = (const float*)d_in[0];
    const float* mem   = (const float*)d_in[1];
    const float* w     = (const float*)d_in[2];
    const float* bias  = (const float*)d_in[3];
    const float* gamma = (const float*)d_in[4];
    const float* beta  = (const float*)d_in[5];
    float* out_mem  = (float*)d_out;                       // [4,2048,64,48]
    float* out_attn = (float*)d_out + (size_t)Bsz * Nn * Kk; // [4,2048,2048]

    k_gemm<<<Mm / 64, 256>>>(sig, mem, w, bias);
    k_bn_stats<<<dim3(64, 2), 128>>>();
    k_bn_final<<<1, 256>>>(gamma, beta);
    k_bn_apply<<<(Mm * Ee + 255) / 256, 256>>>();
    k_zero<<<4096, 256>>>(out_attn, (Bsz * Nn * Nn) / 4);
    k_attn<<<dim3(Nn / 8, Bsz), 256>>>(out_attn);
    k_memw<<<dim3(Nn / 16, 12, Bsz), 256>>>(sig, mem, out_mem);
}

// round 3
// speedup vs baseline: 2.3887x; 2.3887x over previous
#include <cuda_runtime.h>
#include <math.h>
#include <stdint.h>

#define Bsz 4
#define Nn 2048
#define Ee 128
#define Kk 3072            // C*P
#define Mm 16384           // 2*B*N rows (sig half then mem half)
#define HALF_WIN 15
#define NCHUNK 48          // 3072 / 64

// ---------------- scratch ----------------
__device__ float g_embed[Mm * Ee];           // pre-BN y = conv(x)+bias
__device__ float g_psum[2 * 64 * Ee];
__device__ float g_psumsq[2 * 64 * Ee];
__device__ float g_scale[2 * Ee];
__device__ float g_shift[2 * Ee];
__device__ float g_attn_band[Bsz * Nn * 32];

// ---------------- helpers ----------------
__device__ __forceinline__ uint32_t smem_u32(const void* p) {
    uint32_t a;
    asm("{ .reg .u64 t; cvta.to.shared.u64 t, %1; cvt.u32.u64 %0, t; }" : "=r"(a) : "l"(p));
    return a;
}

__device__ __forceinline__ void ldsm4(uint32_t addr, uint32_t* r) {
    asm volatile("ldmatrix.sync.aligned.m8n8.x4.shared.b16 {%0,%1,%2,%3}, [%4];"
                 : "=r"(r[0]), "=r"(r[1]), "=r"(r[2]), "=r"(r[3]) : "r"(addr));
}

__device__ __forceinline__ void mma16816(float* c, const uint32_t* a, const uint32_t* b) {
    asm volatile(
        "mma.sync.aligned.m16n8k16.row.col.f32.bf16.bf16.f32 "
        "{%0,%1,%2,%3}, {%4,%5,%6,%7}, {%8,%9}, {%0,%1,%2,%3};"
        : "+f"(c[0]), "+f"(c[1]), "+f"(c[2]), "+f"(c[3])
        : "r"(a[0]), "r"(a[1]), "r"(a[2]), "r"(a[3]), "r"(b[0]), "r"(b[1]));
}

// ---------------- K1: HMMA embed GEMM (bf16 3-term split) ----------------
// CTA: M=128 x N=128(=E); K chunks of 64 fp32 -> A0,A1,B0,B1 bf16 bufs (SW128),
// double-buffered: 8 x 16KB = 128KB smem.
#define GEMM_SMEM (1024 + 8 * 16384)

__device__ __forceinline__ void conv_store_regs(const float4* pv, char* base0, char* base1,
                                                const uint32_t* offs) {
#pragma unroll
    for (int q = 0; q < 4; q++) {
        float4 u = pv[2 * q];
        float4 v = pv[2 * q + 1];
        uint32_t p0, p1, p2, p3, r0, r1, r2, r3;
        asm("cvt.rn.bf16x2.f32 %0, %1, %2;" : "=r"(p0) : "f"(u.y), "f"(u.x));
        asm("cvt.rn.bf16x2.f32 %0, %1, %2;" : "=r"(p1) : "f"(u.w), "f"(u.z));
        asm("cvt.rn.bf16x2.f32 %0, %1, %2;" : "=r"(p2) : "f"(v.y), "f"(v.x));
        asm("cvt.rn.bf16x2.f32 %0, %1, %2;" : "=r"(p3) : "f"(v.w), "f"(v.z));
        float e0 = u.x - __uint_as_float(p0 << 16);
        float e1 = u.y - __uint_as_float(p0 & 0xffff0000u);
        float e2 = u.z - __uint_as_float(p1 << 16);
        float e3 = u.w - __uint_as_float(p1 & 0xffff0000u);
        float e4 = v.x - __uint_as_float(p2 << 16);
        float e5 = v.y - __uint_as_float(p2 & 0xffff0000u);
        float e6 = v.z - __uint_as_float(p3 << 16);
        float e7 = v.w - __uint_as_float(p3 & 0xffff0000u);
        asm("cvt.rn.bf16x2.f32 %0, %1, %2;" : "=r"(r0) : "f"(e1), "f"(e0));
        asm("cvt.rn.bf16x2.f32 %0, %1, %2;" : "=r"(r1) : "f"(e3), "f"(e2));
        asm("cvt.rn.bf16x2.f32 %0, %1, %2;" : "=r"(r2) : "f"(e5), "f"(e4));
        asm("cvt.rn.bf16x2.f32 %0, %1, %2;" : "=r"(r3) : "f"(e7), "f"(e6));
        *(uint4*)(base0 + offs[q]) = make_uint4(p0, p1, p2, p3);
        *(uint4*)(base1 + offs[q]) = make_uint4(r0, r1, r2, r3);
    }
}

__global__ void __launch_bounds__(256, 1)
k_gemm(const float* __restrict__ sig, const float* __restrict__ mem,
       const float* __restrict__ w, const float* __restrict__ bias) {
    extern __shared__ char smraw[];
    uint32_t sb = smem_u32(smraw);
    uint32_t ab = (sb + 1023) & ~1023u;
    char* sm = smraw + (ab - sb);

    int tid = threadIdx.x;
    int wid = tid >> 5, lane = tid & 31;

    int bm = blockIdx.x * 128;
    const float* X = (bm < 8192) ? sig : mem;
    int rb = (bm < 8192) ? bm : bm - 8192;

    // loader mapping: thread -> (row m, k-half h), 32 contiguous floats
    int m = tid >> 1;
    int h = tid & 1;
    const float* arow = X + (size_t)(rb + m) * Kk + h * 32;
    const float* brow = w + (size_t)m * Kk + h * 32;

    uint32_t offs[4];
#pragma unroll
    for (int q = 0; q < 4; q++) {
        uint32_t o = (uint32_t)m * 128 + (uint32_t)h * 64 + q * 16;
        offs[q] = o ^ ((o >> 3) & 0x70);   // SW128 swizzle
    }

    // warp tile: 4 warps in M (32 rows each) x 2 warps in N (64 cols each)
    int mwrow = (wid >> 1) * 32;
    int nwcol = (wid & 1) * 64;

    float acc[2][8][4];
#pragma unroll
    for (int a = 0; a < 2; a++)
#pragma unroll
        for (int b = 0; b < 8; b++)
#pragma unroll
            for (int c = 0; c < 4; c++) acc[a][b][c] = 0.f;

    // chunk 0: load + convert + store
    {
        float4 pa[8], pb[8];
#pragma unroll
        for (int q = 0; q < 8; q++) pa[q] = *(const float4*)(arow + q * 4);
#pragma unroll
        for (int q = 0; q < 8; q++) pb[q] = *(const float4*)(brow + q * 4);
        conv_store_regs(pa, sm + 0 * 16384, sm + 1 * 16384, offs);
        conv_store_regs(pb, sm + 2 * 16384, sm + 3 * 16384, offs);
    }
    __syncthreads();

    for (int c = 0; c < NCHUNK; c++) {
        int s = c & 1;
        bool more = (c + 1 < NCHUNK);
        float4 pa[8];
        if (more) {
            const float* ap = arow + (c + 1) * 64;
#pragma unroll
            for (int q = 0; q < 8; q++) pa[q] = *(const float4*)(ap + q * 4);
        }

        uint32_t bA0 = ab + (s * 4 + 0) * 16384;
        uint32_t bA1 = ab + (s * 4 + 1) * 16384;
        uint32_t bB0 = ab + (s * 4 + 2) * 16384;
        uint32_t bB1 = ab + (s * 4 + 3) * 16384;

#pragma unroll
        for (int j = 0; j < 4; j++) {
            uint32_t fa0[2][4], fa1[2][4];
#pragma unroll
            for (int mi = 0; mi < 2; mi++) {
                uint32_t row = mwrow + mi * 16 + (lane & 15);
                uint32_t off = row * 128 + ((lane >> 4) * 16) + j * 32;
                off ^= (off >> 3) & 0x70;
                ldsm4(bA0 + off, fa0[mi]);
                ldsm4(bA1 + off, fa1[mi]);
            }
            uint32_t fb0[4][4], fb1[4][4];
#pragma unroll
            for (int p = 0; p < 4; p++) {
                uint32_t rowb = nwcol + p * 16 + (lane & 7) + ((lane >> 4) << 3);
                uint32_t off = rowb * 128 + (((lane >> 3) & 1) * 16) + j * 32;
                off ^= (off >> 3) & 0x70;
                ldsm4(bB0 + off, fb0[p]);
                ldsm4(bB1 + off, fb1[p]);
            }
#pragma unroll
            for (int mi = 0; mi < 2; mi++)
#pragma unroll
                for (int p = 0; p < 4; p++)
#pragma unroll
                    for (int hh = 0; hh < 2; hh++) {
                        int tn = 2 * p + hh;
                        mma16816(acc[mi][tn], fa0[mi], &fb0[p][2 * hh]);
                        mma16816(acc[mi][tn], fa1[mi], &fb0[p][2 * hh]);
                        mma16816(acc[mi][tn], fa0[mi], &fb1[p][2 * hh]);
                    }
        }

        if (more) {
            float4 pb[8];
            const float* bp = brow + (c + 1) * 64;
#pragma unroll
            for (int q = 0; q < 8; q++) pb[q] = *(const float4*)(bp + q * 4);
            int t = (c + 1) & 1;
            conv_store_regs(pa, sm + (t * 4 + 0) * 16384, sm + (t * 4 + 1) * 16384, offs);
            conv_store_regs(pb, sm + (t * 4 + 2) * 16384, sm + (t * 4 + 3) * 16384, offs);
        }
        __syncthreads();
    }

    // epilogue: acc -> g_embed (+bias)
    int g = lane >> 2, t4 = lane & 3;
#pragma unroll
    for (int mi = 0; mi < 2; mi++) {
        int row0 = bm + mwrow + mi * 16 + g;
#pragma unroll
        for (int tn = 0; tn < 8; tn++) {
            int col = nwcol + tn * 8 + 2 * t4;
            float bx = __ldg(&bias[col]);
            float by = __ldg(&bias[col + 1]);
            float2 o0 = make_float2(acc[mi][tn][0] + bx, acc[mi][tn][1] + by);
            float2 o1 = make_float2(acc[mi][tn][2] + bx, acc[mi][tn][3] + by);
            *(float2*)&g_embed[(size_t)row0 * Ee + col] = o0;
            *(float2*)&g_embed[(size_t)(row0 + 8) * Ee + col] = o1;
        }
    }
}

// ---------------- K2: BN partial sums (deterministic) ----------------
__global__ void k_bn_stats() {
    int e = threadIdx.x;
    int chunk = blockIdx.x;
    int half = blockIdx.y;
    int row0 = half * 8192 + chunk * 128;
    float s = 0.f, sq = 0.f;
#pragma unroll 4
    for (int r = 0; r < 128; r++) {
        float v = g_embed[(size_t)(row0 + r) * Ee + e];
        s += v;
        sq += v * v;
    }
    g_psum[(half * 64 + chunk) * Ee + e] = s;
    g_psumsq[(half * 64 + chunk) * Ee + e] = sq;
}

// ---------------- K3: finalize BN scale/shift ----------------
__global__ void k_bn_final(const float* __restrict__ gamma, const float* __restrict__ beta) {
    int t = threadIdx.x;
    int half = t >> 7;
    int e = t & 127;
    float s = 0.f, sq = 0.f;
    for (int c = 0; c < 64; c++) {
        s += g_psum[(half * 64 + c) * Ee + e];
        sq += g_psumsq[(half * 64 + c) * Ee + e];
    }
    float mean = s / 8192.f;
    float var = sq / 8192.f - mean * mean;
    float rstd = rsqrtf(var + 1e-5f);
    float sc = rstd * gamma[e];
    g_scale[t] = sc;
    g_shift[t] = beta[e] - mean * sc;
}

// ---------------- K4: banded sim + softmax (BN folded; full-row writes) ----
__global__ void k_attn(float* __restrict__ out_attn) {
    __shared__ float s_et[38 * 129];
    __shared__ float s_ex[8 * 128];
    __shared__ float s_band[8][32];
    __shared__ float s_sc[256], s_sh[256];
    int i0 = blockIdx.x * 8;
    int b = blockIdx.y;
    int jmin = max(0, i0 - HALF_WIN);
    int jmax = min(Nn - 1, i0 + 7 + HALF_WIN);
    int nj = jmax - jmin + 1;
    int tid = threadIdx.x;

    s_sc[tid] = g_scale[tid];
    s_sh[tid] = g_shift[tid];
    __syncthreads();

    for (int p = tid; p < nj * 128; p += 256) {
        int jr = p >> 7, k = p & 127;
        float v = g_embed[(size_t)(8192 + b * Nn + jmin + jr) * Ee + k] * s_sc[128 + k] + s_sh[128 + k];
        s_et[jr * 129 + k] = (v >= 0.f) ? v : 0.1f * v;
    }
    for (int p = tid; p < 8 * 128; p += 256) {
        int r = p >> 7, k = p & 127;
        float v = g_embed[(size_t)(b * Nn + i0 + r) * Ee + k] * s_sc[k] + s_sh[k];
        s_ex[r * 128 + k] = (v >= 0.f) ? v : 0.1f * v;
    }
    __syncthreads();

    int w = tid >> 5, lane = tid & 31;
    int i = i0 + w;
    int j0 = max(0, i - HALF_WIN);
    int j1 = min(Nn - 1, i + HALF_WIN);
    int width = j1 - j0 + 1;

    float sim = -1e30f;
    if (lane < width) {
        int jr = j0 + lane - jmin;
        float acc = 0.f;
        const float* ex = &s_ex[w * 128];
        const float* et = &s_et[jr * 129];
#pragma unroll 8
        for (int k = 0; k < 128; k++) acc += ex[k] * et[k];
        sim = acc;
    }
    float mx = sim;
#pragma unroll
    for (int o = 16; o; o >>= 1) mx = fmaxf(mx, __shfl_xor_sync(0xffffffffu, mx, o));
    float ev = (lane < width) ? expf(sim - mx) : 0.f;
    float sum = ev;
#pragma unroll
    for (int o = 16; o; o >>= 1) sum += __shfl_xor_sync(0xffffffffu, sum, o);
    float a = ev / sum;
    s_band[w][lane] = (lane < width) ? a : 0.f;
    if (lane < width) g_attn_band[(b * Nn + i) * 32 + lane] = a;
    __syncwarp();

    float* rowp = out_attn + ((size_t)(b * Nn + i)) * Nn;
#pragma unroll
    for (int t = 0; t < 16; t++) {
        int j4 = (t * 32 + lane) * 4;
        float4 o;
#pragma unroll
        for (int q = 0; q < 4; q++) {
            int j = j4 + q;
            ((float*)&o)[q] = (j >= j0 && j <= j1) ? s_band[w][j - j0] : 0.f;
        }
        *(float4*)&rowp[j4] = o;
    }
}

// ---------------- K5: banded attn @ mem + blend ----------------
__global__ void k_memw(const float* __restrict__ sig, const float* __restrict__ mem,
                       float* __restrict__ out_mem) {
    __shared__ float s_attn[16 * 48];
    __shared__ float s_val[23][256];
    int i0 = blockIdx.x * 16;
    int fc = blockIdx.y * 256;
    int b = blockIdx.z;
    int tid = threadIdx.x;
    int jmin = max(0, i0 - HALF_WIN);
    int jmax = min(Nn - 1, i0 + 15 + HALF_WIN);
    int nj = jmax - jmin + 1; // <= 46

    for (int q = tid; q < 16 * 48; q += 256) s_attn[q] = 0.f;
    __syncthreads();
    for (int q = tid; q < 16 * 32; q += 256) {
        int r = q >> 5, l = q & 31;
        int i = i0 + r;
        int j0 = max(0, i - HALF_WIN);
        int j1 = min(Nn - 1, i + HALF_WIN);
        if (l <= j1 - j0)
            s_attn[r * 48 + (j0 + l - jmin)] = g_attn_band[(b * Nn + i) * 32 + l];
    }
    __syncthreads();

    int tf = tid & 63;
    int ti = tid >> 6;
    float acc[4][4];
#pragma unroll
    for (int r = 0; r < 4; r++)
#pragma unroll
        for (int c = 0; c < 4; c++) acc[r][c] = 0.f;

    for (int s = 0; s * 23 < nj; s++) {
        int cnt = min(23, nj - s * 23);
        for (int p = tid; p < cnt * 64; p += 256) {
            int row = p >> 6, c4 = (p & 63) * 4;
            *(float4*)&s_val[row][c4] =
                *(const float4*)&mem[(size_t)(b * Nn + jmin + s * 23 + row) * Kk + fc + c4];
        }
        __syncthreads();
        for (int jl = 0; jl < cnt; jl++) {
            int jg = s * 23 + jl;
            float4 v = *(float4*)&s_val[jl][tf * 4];
#pragma unroll
            for (int r = 0; r < 4; r++) {
                float a = s_attn[(ti * 4 + r) * 48 + jg];
                acc[r][0] += a * v.x;
                acc[r][1] += a * v.y;
                acc[r][2] += a * v.z;
                acc[r][3] += a * v.w;
            }
        }
        __syncthreads();
    }

#pragma unroll
    for (int r = 0; r < 4; r++) {
        int i = i0 + ti * 4 + r;
        size_t base = (size_t)(b * Nn + i) * Kk + fc + tf * 4;
        float4 sg = *(const float4*)&sig[base];
        float4 o;
        o.x = 0.5f * sg.x + 0.5f * acc[r][0];
        o.y = 0.5f * sg.y + 0.5f * acc[r][1];
        o.z = 0.5f * sg.z + 0.5f * acc[r][2];
        o.w = 0.5f * sg.w + 0.5f * acc[r][3];
        *(float4*)&out_mem[base] = o;
    }
}

// ---------------- launch ----------------
extern "C" void kernel_launch(void* const* d_in, const int* in_sizes, int n_in,
                              void* d_out, int out_size) {
    const float* sig   = (const float*)d_in[0];
    const float* mem   = (const float*)d_in[1];
    const float* w     = (const float*)d_in[2];
    const float* bias  = (const float*)d_in[3];
    const float* gamma = (const float*)d_in[4];
    const float* beta  = (const float*)d_in[5];
    float* out_mem  = (float*)d_out;
    float* out_attn = (float*)d_out + (size_t)Bsz * Nn * Kk;

    static bool attr_done = false;
    if (!attr_done) {
        cudaFuncSetAttribute(k_gemm, cudaFuncAttributeMaxDynamicSharedMemorySize, GEMM_SMEM);
        attr_done = true;
    }

    k_gemm<<<Mm / 128, 256, GEMM_SMEM>>>(sig, mem, w, bias);
    k_bn_stats<<<dim3(64, 2), 128>>>();
    k_bn_final<<<1, 256>>>(gamma, beta);
    k_attn<<<dim3(Nn / 8, Bsz), 256>>>(out_attn);
    k_memw<<<dim3(Nn / 16, 12, Bsz), 256>>>(sig, mem, out_mem);
}

// round 4
// speedup vs baseline: 2.5540x; 1.0692x over previous
#include <cuda_runtime.h>
#include <cuda_fp16.h>
#include <math.h>
#include <stdint.h>

#define Bsz 4
#define Nn 2048
#define Ee 128
#define Kk 3072            // C*P
#define Mm 16384           // 2*B*N rows (sig half then mem half)
#define HALF_WIN 15
#define NCHUNK 48          // 3072 / 64

// ---------------- scratch ----------------
__device__ float g_embed[Mm * Ee];           // pre-BN y = conv(x)+bias
__device__ float g_psum[2 * 64 * Ee];
__device__ float g_psumsq[2 * 64 * Ee];
__device__ float g_scale[2 * Ee];
__device__ float g_shift[2 * Ee];
__device__ float g_attn_band[Bsz * Nn * 32];
__device__ uint4 g_w0u[49152];               // W main bf16  [128*3072]
__device__ uint4 g_w1u[49152];               // W residual bf16

// ---------------- helpers ----------------
__device__ __forceinline__ uint32_t smem_u32(const void* p) {
    uint32_t a;
    asm("{ .reg .u64 t; cvta.to.shared.u64 t, %1; cvt.u32.u64 %0, t; }" : "=r"(a) : "l"(p));
    return a;
}

__device__ __forceinline__ void ldsm4(uint32_t addr, uint32_t* r) {
    asm volatile("ldmatrix.sync.aligned.m8n8.x4.shared.b16 {%0,%1,%2,%3}, [%4];"
                 : "=r"(r[0]), "=r"(r[1]), "=r"(r[2]), "=r"(r[3]) : "r"(addr));
}
__device__ __forceinline__ void ldsm2t(uint32_t addr, uint32_t* r) {
    asm volatile("ldmatrix.sync.aligned.m8n8.x2.trans.shared.b16 {%0,%1}, [%2];"
                 : "=r"(r[0]), "=r"(r[1]) : "r"(addr));
}

__device__ __forceinline__ void mma16816(float* c, const uint32_t* a, const uint32_t* b) {
    asm volatile(
        "mma.sync.aligned.m16n8k16.row.col.f32.bf16.bf16.f32 "
        "{%0,%1,%2,%3}, {%4,%5,%6,%7}, {%8,%9}, {%0,%1,%2,%3};"
        : "+f"(c[0]), "+f"(c[1]), "+f"(c[2]), "+f"(c[3])
        : "r"(a[0]), "r"(a[1]), "r"(a[2]), "r"(a[3]), "r"(b[0]), "r"(b[1]));
}
__device__ __forceinline__ void mma16816h(float* c, const uint32_t* a, const uint32_t* b) {
    asm volatile(
        "mma.sync.aligned.m16n8k16.row.col.f32.f16.f16.f32 "
        "{%0,%1,%2,%3}, {%4,%5,%6,%7}, {%8,%9}, {%0,%1,%2,%3};"
        : "+f"(c[0]), "+f"(c[1]), "+f"(c[2]), "+f"(c[3])
        : "r"(a[0]), "r"(a[1]), "r"(a[2]), "r"(a[3]), "r"(b[0]), "r"(b[1]));
}

// ---------------- K0: pre-split W into bf16 main + residual ----------------
__global__ void k_wsplit(const float* __restrict__ w) {
    int t = blockIdx.x * blockDim.x + threadIdx.x;   // 49152 threads, 8 floats each
    int i0 = t * 8;
    float4 u = *(const float4*)&w[i0];
    float4 v = *(const float4*)&w[i0 + 4];
    uint32_t p0, p1, p2, p3, r0, r1, r2, r3;
    asm("cvt.rn.bf16x2.f32 %0, %1, %2;" : "=r"(p0) : "f"(u.y), "f"(u.x));
    asm("cvt.rn.bf16x2.f32 %0, %1, %2;" : "=r"(p1) : "f"(u.w), "f"(u.z));
    asm("cvt.rn.bf16x2.f32 %0, %1, %2;" : "=r"(p2) : "f"(v.y), "f"(v.x));
    asm("cvt.rn.bf16x2.f32 %0, %1, %2;" : "=r"(p3) : "f"(v.w), "f"(v.z));
    float e0 = u.x - __uint_as_float(p0 << 16);
    float e1 = u.y - __uint_as_float(p0 & 0xffff0000u);
    float e2 = u.z - __uint_as_float(p1 << 16);
    float e3 = u.w - __uint_as_float(p1 & 0xffff0000u);
    float e4 = v.x - __uint_as_float(p2 << 16);
    float e5 = v.y - __uint_as_float(p2 & 0xffff0000u);
    float e6 = v.z - __uint_as_float(p3 << 16);
    float e7 = v.w - __uint_as_float(p3 & 0xffff0000u);
    asm("cvt.rn.bf16x2.f32 %0, %1, %2;" : "=r"(r0) : "f"(e1), "f"(e0));
    asm("cvt.rn.bf16x2.f32 %0, %1, %2;" : "=r"(r1) : "f"(e3), "f"(e2));
    asm("cvt.rn.bf16x2.f32 %0, %1, %2;" : "=r"(r2) : "f"(e5), "f"(e4));
    asm("cvt.rn.bf16x2.f32 %0, %1, %2;" : "=r"(r3) : "f"(e7), "f"(e6));
    g_w0u[t] = make_uint4(p0, p1, p2, p3);
    g_w1u[t] = make_uint4(r0, r1, r2, r3);
}

// ---------------- K1: HMMA embed GEMM (bf16 3-term split) ----------------
#define GEMM_SMEM (1024 + 8 * 16384)

__device__ __forceinline__ void conv_store_regs(const float4* pv, char* base0, char* base1,
                                                const uint32_t* offs) {
#pragma unroll
    for (int q = 0; q < 4; q++) {
        float4 u = pv[2 * q];
        float4 v = pv[2 * q + 1];
        uint32_t p0, p1, p2, p3, r0, r1, r2, r3;
        asm("cvt.rn.bf16x2.f32 %0, %1, %2;" : "=r"(p0) : "f"(u.y), "f"(u.x));
        asm("cvt.rn.bf16x2.f32 %0, %1, %2;" : "=r"(p1) : "f"(u.w), "f"(u.z));
        asm("cvt.rn.bf16x2.f32 %0, %1, %2;" : "=r"(p2) : "f"(v.y), "f"(v.x));
        asm("cvt.rn.bf16x2.f32 %0, %1, %2;" : "=r"(p3) : "f"(v.w), "f"(v.z));
        float e0 = u.x - __uint_as_float(p0 << 16);
        float e1 = u.y - __uint_as_float(p0 & 0xffff0000u);
        float e2 = u.z - __uint_as_float(p1 << 16);
        float e3 = u.w - __uint_as_float(p1 & 0xffff0000u);
        float e4 = v.x - __uint_as_float(p2 << 16);
        float e5 = v.y - __uint_as_float(p2 & 0xffff0000u);
        float e6 = v.z - __uint_as_float(p3 << 16);
        float e7 = v.w - __uint_as_float(p3 & 0xffff0000u);
        asm("cvt.rn.bf16x2.f32 %0, %1, %2;" : "=r"(r0) : "f"(e1), "f"(e0));
        asm("cvt.rn.bf16x2.f32 %0, %1, %2;" : "=r"(r1) : "f"(e3), "f"(e2));
        asm("cvt.rn.bf16x2.f32 %0, %1, %2;" : "=r"(r2) : "f"(e5), "f"(e4));
        asm("cvt.rn.bf16x2.f32 %0, %1, %2;" : "=r"(r3) : "f"(e7), "f"(e6));
        *(uint4*)(base0 + offs[q]) = make_uint4(p0, p1, p2, p3);
        *(uint4*)(base1 + offs[q]) = make_uint4(r0, r1, r2, r3);
    }
}

__global__ void __launch_bounds__(256, 1)
k_gemm(const float* __restrict__ sig, const float* __restrict__ mem,
       const float* __restrict__ bias) {
    extern __shared__ char smraw[];
    uint32_t sb = smem_u32(smraw);
    uint32_t ab = (sb + 1023) & ~1023u;
    char* sm = smraw + (ab - sb);

    int tid = threadIdx.x;
    int wid = tid >> 5, lane = tid & 31;

    int bm = blockIdx.x * 128;
    const float* X = (bm < 8192) ? sig : mem;
    int rb = (bm < 8192) ? bm : bm - 8192;

    int m = tid >> 1;
    int h = tid & 1;
    const float* arow = X + (size_t)(rb + m) * Kk + h * 32;
    const uint4* b0p = g_w0u + m * 384 + h * 4;   // per chunk: + c*8
    const uint4* b1p = g_w1u + m * 384 + h * 4;

    uint32_t offs[4];
#pragma unroll
    for (int q = 0; q < 4; q++) {
        uint32_t o = (uint32_t)m * 128 + (uint32_t)h * 64 + q * 16;
        offs[q] = o ^ ((o >> 3) & 0x70);   // SW128 swizzle
    }

    int mwrow = (wid >> 1) * 32;
    int nwcol = (wid & 1) * 64;

    float acc[2][8][4];
#pragma unroll
    for (int a = 0; a < 2; a++)
#pragma unroll
        for (int b = 0; b < 8; b++)
#pragma unroll
            for (int c = 0; c < 4; c++) acc[a][b][c] = 0.f;

    // chunk 0
    {
        float4 pa[8];
#pragma unroll
        for (int q = 0; q < 8; q++) pa[q] = *(const float4*)(arow + q * 4);
        conv_store_regs(pa, sm + 0 * 16384, sm + 1 * 16384, offs);
#pragma unroll
        for (int q = 0; q < 4; q++) {
            *(uint4*)(sm + 2 * 16384 + offs[q]) = b0p[q];
            *(uint4*)(sm + 3 * 16384 + offs[q]) = b1p[q];
        }
    }
    __syncthreads();

    for (int c = 0; c < NCHUNK; c++) {
        int s = c & 1;
        bool more = (c + 1 < NCHUNK);
        float4 pa[8];
        uint4 qb0[4], qb1[4];
        if (more) {
            const float* ap = arow + (c + 1) * 64;
#pragma unroll
            for (int q = 0; q < 8; q++) pa[q] = *(const float4*)(ap + q * 4);
#pragma unroll
            for (int q = 0; q < 4; q++) {
                qb0[q] = b0p[(c + 1) * 8 + q];
                qb1[q] = b1p[(c + 1) * 8 + q];
            }
        }

        uint32_t bA0 = ab + (s * 4 + 0) * 16384;
        uint32_t bA1 = ab + (s * 4 + 1) * 16384;
        uint32_t bB0 = ab + (s * 4 + 2) * 16384;
        uint32_t bB1 = ab + (s * 4 + 3) * 16384;

#pragma unroll
        for (int j = 0; j < 4; j++) {
            uint32_t fa0[2][4], fa1[2][4];
#pragma unroll
            for (int mi = 0; mi < 2; mi++) {
                uint32_t row = mwrow + mi * 16 + (lane & 15);
                uint32_t off = row * 128 + ((lane >> 4) * 16) + j * 32;
                off ^= (off >> 3) & 0x70;
                ldsm4(bA0 + off, fa0[mi]);
                ldsm4(bA1 + off, fa1[mi]);
            }
            uint32_t fb0[4][4], fb1[4][4];
#pragma unroll
            for (int p = 0; p < 4; p++) {
                uint32_t rowb = nwcol + p * 16 + (lane & 7) + ((lane >> 4) << 3);
                uint32_t off = rowb * 128 + (((lane >> 3) & 1) * 16) + j * 32;
                off ^= (off >> 3) & 0x70;
                ldsm4(bB0 + off, fb0[p]);
                ldsm4(bB1 + off, fb1[p]);
            }
#pragma unroll
            for (int mi = 0; mi < 2; mi++)
#pragma unroll
                for (int p = 0; p < 4; p++)
#pragma unroll
                    for (int hh = 0; hh < 2; hh++) {
                        int tn = 2 * p + hh;
                        mma16816(acc[mi][tn], fa0[mi], &fb0[p][2 * hh]);
                        mma16816(acc[mi][tn], fa1[mi], &fb0[p][2 * hh]);
                        mma16816(acc[mi][tn], fa0[mi], &fb1[p][2 * hh]);
                    }
        }

        if (more) {
            int t = (c + 1) & 1;
            conv_store_regs(pa, sm + (t * 4 + 0) * 16384, sm + (t * 4 + 1) * 16384, offs);
#pragma unroll
            for (int q = 0; q < 4; q++) {
                *(uint4*)(sm + (t * 4 + 2) * 16384 + offs[q]) = qb0[q];
                *(uint4*)(sm + (t * 4 + 3) * 16384 + offs[q]) = qb1[q];
            }
        }
        __syncthreads();
    }

    int g = lane >> 2, t4 = lane & 3;
#pragma unroll
    for (int mi = 0; mi < 2; mi++) {
        int row0 = bm + mwrow + mi * 16 + g;
#pragma unroll
        for (int tn = 0; tn < 8; tn++) {
            int col = nwcol + tn * 8 + 2 * t4;
            float bx = __ldg(&bias[col]);
            float by = __ldg(&bias[col + 1]);
            float2 o0 = make_float2(acc[mi][tn][0] + bx, acc[mi][tn][1] + by);
            float2 o1 = make_float2(acc[mi][tn][2] + bx, acc[mi][tn][3] + by);
            *(float2*)&g_embed[(size_t)row0 * Ee + col] = o0;
            *(float2*)&g_embed[(size_t)(row0 + 8) * Ee + col] = o1;
        }
    }
}

// ---------------- K2: BN partial sums (deterministic) ----------------
__global__ void k_bn_stats() {
    int e = threadIdx.x;
    int chunk = blockIdx.x;
    int half = blockIdx.y;
    int row0 = half * 8192 + chunk * 128;
    float s = 0.f, sq = 0.f;
#pragma unroll 4
    for (int r = 0; r < 128; r++) {
        float v = g_embed[(size_t)(row0 + r) * Ee + e];
        s += v;
        sq += v * v;
    }
    g_psum[(half * 64 + chunk) * Ee + e] = s;
    g_psumsq[(half * 64 + chunk) * Ee + e] = sq;
}

// ---------------- K3: finalize BN scale/shift ----------------
__global__ void k_bn_final(const float* __restrict__ gamma, const float* __restrict__ beta) {
    int t = threadIdx.x;
    int half = t >> 7;
    int e = t & 127;
    float s = 0.f, sq = 0.f;
    for (int c = 0; c < 64; c++) {
        s += g_psum[(half * 64 + c) * Ee + e];
        sq += g_psumsq[(half * 64 + c) * Ee + e];
    }
    float mean = s / 8192.f;
    float var = sq / 8192.f - mean * mean;
    float rstd = rsqrtf(var + 1e-5f);
    float sc = rstd * gamma[e];
    g_scale[t] = sc;
    g_shift[t] = beta[e] - mean * sc;
}

// ---------------- K4: banded sim + softmax (BN folded; full-row writes) ----
__global__ void k_attn(float* __restrict__ out_attn) {
    __shared__ float s_et[38 * 129];
    __shared__ float s_ex[8 * 128];
    __shared__ float s_band[8][32];
    __shared__ float s_sc[256], s_sh[256];
    int i0 = blockIdx.x * 8;
    int b = blockIdx.y;
    int jmin = max(0, i0 - HALF_WIN);
    int jmax = min(Nn - 1, i0 + 7 + HALF_WIN);
    int nj = jmax - jmin + 1;
    int tid = threadIdx.x;

    s_sc[tid] = g_scale[tid];
    s_sh[tid] = g_shift[tid];
    __syncthreads();

    for (int p = tid; p < nj * 128; p += 256) {
        int jr = p >> 7, k = p & 127;
        float v = g_embed[(size_t)(8192 + b * Nn + jmin + jr) * Ee + k] * s_sc[128 + k] + s_sh[128 + k];
        s_et[jr * 129 + k] = (v >= 0.f) ? v : 0.1f * v;
    }
    for (int p = tid; p < 8 * 128; p += 256) {
        int r = p >> 7, k = p & 127;
        float v = g_embed[(size_t)(b * Nn + i0 + r) * Ee + k] * s_sc[k] + s_sh[k];
        s_ex[r * 128 + k] = (v >= 0.f) ? v : 0.1f * v;
    }
    __syncthreads();

    int w = tid >> 5, lane = tid & 31;
    int i = i0 + w;
    int j0 = max(0, i - HALF_WIN);
    int j1 = min(Nn - 1, i + HALF_WIN);
    int width = j1 - j0 + 1;

    float sim = -1e30f;
    if (lane < width) {
        int jr = j0 + lane - jmin;
        float acc = 0.f;
        const float* ex = &s_ex[w * 128];
        const float* et = &s_et[jr * 129];
#pragma unroll 8
        for (int k = 0; k < 128; k++) acc += ex[k] * et[k];
        sim = acc;
    }
    float mx = sim;
#pragma unroll
    for (int o = 16; o; o >>= 1) mx = fmaxf(mx, __shfl_xor_sync(0xffffffffu, mx, o));
    float ev = (lane < width) ? expf(sim - mx) : 0.f;
    float sum = ev;
#pragma unroll
    for (int o = 16; o; o >>= 1) sum += __shfl_xor_sync(0xffffffffu, sum, o);
    float a = ev / sum;
    s_band[w][lane] = (lane < width) ? a : 0.f;
    if (lane < width) g_attn_band[(b * Nn + i) * 32 + lane] = a;
    __syncwarp();

    float* rowp = out_attn + ((size_t)(b * Nn + i)) * Nn;
#pragma unroll
    for (int t = 0; t < 16; t++) {
        int j4 = (t * 32 + lane) * 4;
        float4 o = make_float4(0.f, 0.f, 0.f, 0.f);
        if (j4 + 3 >= j0 && j4 <= j1) {
#pragma unroll
            for (int q = 0; q < 4; q++) {
                int j = j4 + q;
                if (j >= j0 && j <= j1) ((float*)&o)[q] = s_band[w][j - j0];
            }
        }
        *(float4*)&rowp[j4] = o;
    }
}

// ---------------- K5: banded attn @ mem via fp16 HMMA + blend --------------
// block = 16 rows x 256 f; K = band union padded to 48; 8 warps, 4 n8-tiles each
__global__ void __launch_bounds__(256)
k_memw(const float* __restrict__ sig, const float* __restrict__ mem,
       float* __restrict__ out_mem) {
    __shared__ __half s_a0[16][56];
    __shared__ __half s_a1[16][56];
    __shared__ __half s_m[48][264];
    __shared__ float s_out[16][256];
    int i0 = blockIdx.x * 16;
    int fc = blockIdx.y * 256;
    int b = blockIdx.z;
    int tid = threadIdx.x;
    int jmin = max(0, i0 - HALF_WIN);
    int jmax = min(Nn - 1, i0 + 15 + HALF_WIN);
    int nj = jmax - jmin + 1; // <= 46

    for (int p = tid; p < 16 * 28; p += 256) {
        ((uint32_t*)s_a0)[p] = 0u;
        ((uint32_t*)s_a1)[p] = 0u;
    }
    __syncthreads();
    for (int q = tid; q < 16 * 32; q += 256) {
        int r = q >> 5, l = q & 31;
        int i = i0 + r;
        int j0 = max(0, i - HALF_WIN);
        int j1 = min(Nn - 1, i + HALF_WIN);
        if (l <= j1 - j0) {
            float a = g_attn_band[(b * Nn + i) * 32 + l];
            __half a0 = __float2half_rn(a);
            float res = a - __half2float(a0);
            s_a0[r][j0 - jmin + l] = a0;
            s_a1[r][j0 - jmin + l] = __float2half_rn(res);
        }
    }
    for (int p = tid; p < 48 * 64; p += 256) {
        int row = p >> 6, f4 = (p & 63) * 4;
        __half2 h0, h1;
        if (row < nj) {
            float4 v = *(const float4*)&mem[(size_t)(b * Nn + jmin + row) * Kk + fc + f4];
            h0 = __floats2half2_rn(v.x, v.y);
            h1 = __floats2half2_rn(v.z, v.w);
        } else {
            h0 = __floats2half2_rn(0.f, 0.f);
            h1 = h0;
        }
        *(__half2*)&s_m[row][f4] = h0;
        *(__half2*)&s_m[row][f4 + 2] = h1;
    }
    __syncthreads();

    int wid = tid >> 5, lane = tid & 31;
    uint32_t a0base = smem_u32(&s_a0[0][0]);
    uint32_t a1base = smem_u32(&s_a1[0][0]);
    uint32_t mbase = smem_u32(&s_m[0][0]);

    float acc[4][4];
#pragma unroll
    for (int t = 0; t < 4; t++)
#pragma unroll
        for (int c = 0; c < 4; c++) acc[t][c] = 0.f;

#pragma unroll
    for (int ks = 0; ks < 3; ks++) {
        uint32_t fa0[4], fa1[4];
        {
            uint32_t row = lane & 15;
            uint32_t coloff = ks * 16 + (lane >> 4) * 8;
            ldsm4(a0base + (row * 56 + coloff) * 2, fa0);
            ldsm4(a1base + (row * 56 + coloff) * 2, fa1);
        }
#pragma unroll
        for (int t = 0; t < 4; t++) {
            uint32_t ncol = (wid * 4 + t) * 8;
            uint32_t krow = ks * 16 + (lane & 15);
            uint32_t fb[2];
            ldsm2t(mbase + (krow * 264 + ncol) * 2, fb);
            mma16816h(acc[t], fa0, fb);
            mma16816h(acc[t], fa1, fb);
        }
    }

    int g = lane >> 2, c2 = (lane & 3) * 2;
#pragma unroll
    for (int t = 0; t < 4; t++) {
        int cb = wid * 32 + t * 8 + c2;
        s_out[g][cb] = acc[t][0];
        s_out[g][cb + 1] = acc[t][1];
        s_out[g + 8][cb] = acc[t][2];
        s_out[g + 8][cb + 1] = acc[t][3];
    }
    __syncthreads();

    for (int p = tid; p < 16 * 64; p += 256) {
        int r = p >> 6, f4 = (p & 63) * 4;
        size_t base = (size_t)(b * Nn + i0 + r) * Kk + fc + f4;
        float4 sg = *(const float4*)&sig[base];
        float4 mv = *(float4*)&s_out[r][f4];
        float4 o;
        o.x = 0.5f * sg.x + 0.5f * mv.x;
        o.y = 0.5f * sg.y + 0.5f * mv.y;
        o.z = 0.5f * sg.z + 0.5f * mv.z;
        o.w = 0.5f * sg.w + 0.5f * mv.w;
        *(float4*)&out_mem[base] = o;
    }
}

// ---------------- launch ----------------
extern "C" void kernel_launch(void* const* d_in, const int* in_sizes, int n_in,
                              void* d_out, int out_size) {
    const float* sig   = (const float*)d_in[0];
    const float* mem   = (const float*)d_in[1];
    const float* w     = (const float*)d_in[2];
    const float* bias  = (const float*)d_in[3];
    const float* gamma = (const float*)d_in[4];
    const float* beta  = (const float*)d_in[5];
    float* out_mem  = (float*)d_out;
    float* out_attn = (float*)d_out + (size_t)Bsz * Nn * Kk;

    static bool attr_done = false;
    if (!attr_done) {
        cudaFuncSetAttribute(k_gemm, cudaFuncAttributeMaxDynamicSharedMemorySize, GEMM_SMEM);
        attr_done = true;
    }

    k_wsplit<<<192, 256>>>(w);
    k_gemm<<<Mm / 128, 256, GEMM_SMEM>>>(sig, mem, bias);
    k_bn_stats<<<dim3(64, 2), 128>>>();
    k_bn_final<<<1, 256>>>(gamma, beta);
    k_attn<<<dim3(Nn / 8, Bsz), 256>>>(out_attn);
    k_memw<<<dim3(Nn / 16, 12, Bsz), 256>>>(sig, mem, out_mem);
}